// round 6
// baseline (speedup 1.0000x reference)
#include <cuda_runtime.h>

#define F 1024
#define KDIM 4096          // 4 * F
#define SPLITK 4
#define KCHUNK 1024        // KDIM / SPLITK

// ---- fused-grid layout -----------------------------------------------------
#define GEMM_BLOCKS 128        // (M/64=2) x (N/64=16) x SPLITK
#define COMBINE_BLOCKS 8
#define N_SRC_MEM1 511         // memory rows r = 1..511   (conv region)
#define N_SRC_MEM2 508         // memory rows s = 516..1023 (short region)
#define N_SRC_INP  512         // input rows j = 0..511
#define FAN 4                  // dest-fanout split per source row
#define SCATTER_BASE (GEMM_BLOCKS + COMBINE_BLOCKS)                    // 136
#define NONCOMP_BLOCKS ((N_SRC_MEM1 + N_SRC_MEM2 + N_SRC_INP) * FAN)   // 6124
#define COMP_BASE (SCATTER_BASE + NONCOMP_BLOCKS)                      // 6260
#define COMP_BLOCKS (128 * FAN)                                        // 512
#define TOTAL_BLOCKS (COMP_BASE + COMP_BLOCKS)                         // 6772

// Scratch (no cudaMalloc allowed)
__device__ float g_part[SPLITK][128][F];   // 2 MB split-K partials
__device__ float g_comp[128][F];           // 0.5 MB combined comp matrix
__device__ unsigned g_flags[2];            // [0]=gemm done count, [1]=combine done

// ---------------------------------------------------------------------------
// One fused kernel:
//   blocks [0,128)        : split-K fp32 GEMM  comp = X[128,4096] @ W[4096,1024]
//   blocks [128,136)      : spin on flag0, combine partials + bias -> g_comp
//   blocks [136,6260)     : scatter-copy of rows NOT depending on comp
//   blocks [6260,6772)    : scatter-copy of comp rows (grid tail; spin flag1)
//
// Scatter inversion of the gather map (each source row written to all its
// output destinations, read ONCE):
//   memory[r], r=1..511   -> (b, r-b-1)          for b = 0..min(r-1,127)
//   memory[516+d], d<508  -> (b, 512+d-4b)       for b = 0..min(d>>2,126)
//   inputs[j],  j=0..511  -> (b, 1020-4b+j)      for b = (j>>2)..127
//   comp[c],    c=0..127  -> (b, 511-b+c)        for b = c..127
// ---------------------------------------------------------------------------
__global__ __launch_bounds__(256) void OSAR_fused(
    const float* __restrict__ inputs, const float* __restrict__ memory,
    const float* __restrict__ W, const float* __restrict__ bias,
    float* __restrict__ out)
{
    const int bid = blockIdx.x;
    const int tid = threadIdx.x;

    __shared__ float As[16][64];   // A tile, transposed: As[k][m]
    __shared__ float Bs[16][64];   // B tile: Bs[k][n]

    // ================= GEMM blocks =================
    if (bid < GEMM_BLOCKS) {
        const int kz = bid & 3;
        const int bn = (bid >> 2) & 15;
        const int bm = bid >> 6;

        const float* Xb = memory + 512 * F + bm * 64 * KDIM + kz * KCHUNK;
        const float* Wb = W + (size_t)kz * KCHUNK * F + bn * 64;

        const int ar  = tid >> 2, ak  = tid & 3;    // A load: row, 4-float k slot
        const int brk = tid >> 4, bn4 = tid & 15;   // B load: k row, 4-float n slot
        const int ty  = tid >> 4, tx  = tid & 15;   // microtile coords

        float acc[4][4] = {};

        for (int kk = 0; kk < KCHUNK; kk += 16) {
            float4 av = *(const float4*)(Xb + ar * KDIM + kk + ak * 4);
            As[ak * 4 + 0][ar] = av.x;
            As[ak * 4 + 1][ar] = av.y;
            As[ak * 4 + 2][ar] = av.z;
            As[ak * 4 + 3][ar] = av.w;
            float4 bv = *(const float4*)(Wb + (size_t)(kk + brk) * F + bn4 * 4);
            *(float4*)&Bs[brk][bn4 * 4] = bv;
            __syncthreads();
#pragma unroll
            for (int k = 0; k < 16; k++) {
                float4 a = *(float4*)&As[k][ty * 4];
                float4 b = *(float4*)&Bs[k][tx * 4];
                acc[0][0] += a.x * b.x; acc[0][1] += a.x * b.y;
                acc[0][2] += a.x * b.z; acc[0][3] += a.x * b.w;
                acc[1][0] += a.y * b.x; acc[1][1] += a.y * b.y;
                acc[1][2] += a.y * b.z; acc[1][3] += a.y * b.w;
                acc[2][0] += a.z * b.x; acc[2][1] += a.z * b.y;
                acc[2][2] += a.z * b.z; acc[2][3] += a.z * b.w;
                acc[3][0] += a.w * b.x; acc[3][1] += a.w * b.y;
                acc[3][2] += a.w * b.z; acc[3][3] += a.w * b.w;
            }
            __syncthreads();
        }

        float* dst = &g_part[kz][bm * 64 + ty * 4][bn * 64 + tx * 4];
#pragma unroll
        for (int i = 0; i < 4; i++)
            *(float4*)(dst + (size_t)i * F) =
                make_float4(acc[i][0], acc[i][1], acc[i][2], acc[i][3]);

        __syncthreads();
        if (tid == 0) { __threadfence(); atomicAdd(&g_flags[0], 1u); }
        return;
    }

    // ================= combine blocks =================
    if (bid < SCATTER_BASE) {
        if (tid == 0) {
            while (((volatile unsigned*)g_flags)[0] < GEMM_BLOCKS) __nanosleep(64);
        }
        __syncthreads();

        const int base = (bid - GEMM_BLOCKS) * 16384;   // 128*1024 / 8
        const float* p = &g_part[0][0][0];
        float* c = &g_comp[0][0];
        for (int i = tid * 4; i < 16384; i += 1024) {
            int idx = base + i;
            float4 v0 = *(const float4*)(p + idx);
            float4 v1 = *(const float4*)(p + 131072 + idx);
            float4 v2 = *(const float4*)(p + 262144 + idx);
            float4 v3 = *(const float4*)(p + 393216 + idx);
            float4 bb = *(const float4*)(bias + (idx & (F - 1)));
            float4 r;
            r.x = v0.x + v1.x + v2.x + v3.x + bb.x;
            r.y = v0.y + v1.y + v2.y + v3.y + bb.y;
            r.z = v0.z + v1.z + v2.z + v3.z + bb.z;
            r.w = v0.w + v1.w + v2.w + v3.w + bb.w;
            *(float4*)(c + idx) = r;
        }
        __syncthreads();
        if (tid == 0) { __threadfence(); atomicAdd(&g_flags[1], 1u); }
        return;
    }

    float4* out4 = (float4*)out;

    // ================= non-comp scatter blocks =================
    if (bid < COMP_BASE) {
        const int cid = bid - SCATTER_BASE;
        const int sid = cid >> 2;
        const int y   = cid & 3;

        if (sid < N_SRC_MEM1) {
            const int r = sid + 1;                      // memory row 1..511
            const int cnt = min(r, 128);
            const float4 v = ((const float4*)(memory + (size_t)r * F))[tid];
            for (int b = y; b < cnt; b += FAN)
                out4[(size_t)(b * 1024 + (r - b - 1)) * 256 + tid] = v;
        } else if (sid < N_SRC_MEM1 + N_SRC_MEM2) {
            const int d = sid - N_SRC_MEM1;             // 0..507
            const int cnt = min(d >> 2, 126) + 1;
            const float4 v = ((const float4*)(memory + (size_t)(516 + d) * F))[tid];
            for (int b = y; b < cnt; b += FAN)
                out4[(size_t)(b * 1024 + 512 + d - 4 * b) * 256 + tid] = v;
        } else {
            const int j = sid - (N_SRC_MEM1 + N_SRC_MEM2);  // 0..511
            const int b0 = j >> 2;
            const float4 v = ((const float4*)(inputs + (size_t)j * F))[tid];
            for (int b = b0 + y; b < 128; b += FAN)
                out4[(size_t)(b * 1024 + 1020 - 4 * b + j) * 256 + tid] = v;
        }
        return;
    }

    // ================= comp scatter blocks (grid tail) =================
    {
        const int cid = bid - COMP_BASE;
        const int c = cid >> 2;
        const int y = cid & 3;

        if (tid == 0) {
            while (((volatile unsigned*)g_flags)[1] < COMBINE_BLOCKS) __nanosleep(64);
        }
        __syncthreads();

        const float4 v = ((const float4*)g_comp[c])[tid];
        for (int b = c + y; b < 128; b += FAN)
            out4[(size_t)(b * 1024 + 511 - b + c) * 256 + tid] = v;
    }
}

// ---------------------------------------------------------------------------
extern "C" void kernel_launch(void* const* d_in, const int* in_sizes, int n_in,
                              void* d_out, int out_size) {
    const float* inputs = (const float*)d_in[0];   // (128, 4, 1024)
    const float* memory = (const float*)d_in[1];   // (1024, 1024)
    const float* kern   = (const float*)d_in[2];   // (4, 1024, 1024)
    const float* bias   = (const float*)d_in[3];   // (1024,)
    float* out = (float*)d_out;                    // (128, 1024, 1024)

    void* flagsAddr = nullptr;
    cudaGetSymbolAddress(&flagsAddr, g_flags);
    cudaMemsetAsync(flagsAddr, 0, 2 * sizeof(unsigned));

    OSAR_fused<<<TOTAL_BLOCKS, 256>>>(inputs, memory, kern, bias, out);
}

// round 8
// speedup vs baseline: 1.7260x; 1.7260x over previous
#include <cuda_runtime.h>

#define F 1024
#define KDIM 4096            // 4 * F
#define SPLITK 8
#define KCHUNK 512           // KDIM / SPLITK
#define NTILES 32            // KCHUNK / 16

// Scratch (no cudaMalloc allowed): split-K partials.
__device__ float g_part[SPLITK][128][F];     // 4 MB

// ---------------------------------------------------------------------------
// Kernel 1: split-K fp32 GEMM   part[kz] = X[128,4096] @ W[4096,1024]
//   X = memory + 512*F (rows 512..1023 flattened row-major 128 x 4096)
//   W = kernel flattened (4096 x 1024 row-major)
// 64x64 block tile, BK=16, 256 threads, 4x4 microtile, smem DOUBLE-BUFFERED
// with register prefetch (one __syncthreads per k-tile; loads overlap FMA).
// Grid: (N/64=16, M/64=2, SPLITK=8) = 256 blocks.
// ---------------------------------------------------------------------------
__global__ __launch_bounds__(256) void OSAR_gemm(const float* __restrict__ X,
                                                 const float* __restrict__ W) {
    __shared__ float As[2][16][64];   // As[buf][k][m]  (A transposed)
    __shared__ float Bs[2][16][64];   // Bs[buf][k][n]

    const int bn = blockIdx.x;        // 0..15
    const int bm = blockIdx.y;        // 0..1
    const int kz = blockIdx.z;        // 0..7
    const int tid = threadIdx.x;

    const float* Xb = X + bm * 64 * KDIM + kz * KCHUNK;
    const float* Wb = W + (size_t)kz * KCHUNK * F + bn * 64;

    const int ar  = tid >> 2, ak  = tid & 3;    // A load: m-row, k float4 slot
    const int brk = tid >> 4, bn4 = tid & 15;   // B load: k-row, n float4 slot
    const int ty  = tid >> 4, tx  = tid & 15;   // microtile coords (16x16 grid)

    float acc[4][4] = {};

    // preload tile 0
    float4 av = *(const float4*)(Xb + ar * KDIM + ak * 4);
    float4 bv = *(const float4*)(Wb + (size_t)brk * F + bn4 * 4);
    As[0][ak * 4 + 0][ar] = av.x;
    As[0][ak * 4 + 1][ar] = av.y;
    As[0][ak * 4 + 2][ar] = av.z;
    As[0][ak * 4 + 3][ar] = av.w;
    *(float4*)&Bs[0][brk][bn4 * 4] = bv;
    __syncthreads();

    int cur = 0;
    for (int t = 0; t < NTILES; t++) {
        if (t + 1 < NTILES) {   // prefetch next tile into registers
            av = *(const float4*)(Xb + ar * KDIM + (t + 1) * 16 + ak * 4);
            bv = *(const float4*)(Wb + (size_t)((t + 1) * 16 + brk) * F + bn4 * 4);
        }
#pragma unroll
        for (int k = 0; k < 16; k++) {
            float4 a = *(float4*)&As[cur][k][ty * 4];
            float4 b = *(float4*)&Bs[cur][k][tx * 4];
            acc[0][0] += a.x * b.x; acc[0][1] += a.x * b.y;
            acc[0][2] += a.x * b.z; acc[0][3] += a.x * b.w;
            acc[1][0] += a.y * b.x; acc[1][1] += a.y * b.y;
            acc[1][2] += a.y * b.z; acc[1][3] += a.y * b.w;
            acc[2][0] += a.z * b.x; acc[2][1] += a.z * b.y;
            acc[2][2] += a.z * b.z; acc[2][3] += a.z * b.w;
            acc[3][0] += a.w * b.x; acc[3][1] += a.w * b.y;
            acc[3][2] += a.w * b.z; acc[3][3] += a.w * b.w;
        }
        if (t + 1 < NTILES) {   // stage prefetched tile into the other buffer
            int nxt = cur ^ 1;
            As[nxt][ak * 4 + 0][ar] = av.x;
            As[nxt][ak * 4 + 1][ar] = av.y;
            As[nxt][ak * 4 + 2][ar] = av.z;
            As[nxt][ak * 4 + 3][ar] = av.w;
            *(float4*)&Bs[nxt][brk][bn4 * 4] = bv;
        }
        __syncthreads();
        cur ^= 1;
    }

    float* dst = &g_part[kz][bm * 64 + ty * 4][bn * 64 + tx * 4];
#pragma unroll
    for (int i = 0; i < 4; i++)
        *(float4*)(dst + (size_t)i * F) =
            make_float4(acc[i][0], acc[i][1], acc[i][2], acc[i][3]);
}

// ---------------------------------------------------------------------------
// Kernel 2: scatter-copy of the 128 x 1024 x 1024 output (inversion of the
// gather map — each source row read ONCE, written to all its destinations).
//   memory[r], r=1..511   -> (b, r-b-1)       for b = 0..min(r-1,127)
//   memory[516+d], d<508  -> (b, 512+d-4b)    for b = 0..(d>>2) [<=126]
//   inputs[j],  j=0..511  -> (b, 1020-4b+j)   for b = (j>>2)..127
//   comp[c],    c=0..127  -> (b, 511-b+c)     for b = c..127
// comp rows combine the SPLITK partials + bias inline (no separate kernel).
// FAN=4 blocks share each source row's destination fanout.
// ---------------------------------------------------------------------------
#define N_SRC_MEM1 511
#define N_SRC_MEM2 508
#define N_SRC_INP  512
#define FAN 4
#define SCATTER_BLOCKS ((N_SRC_MEM1 + N_SRC_MEM2 + N_SRC_INP + 128) * FAN)  // 6636

__global__ __launch_bounds__(256) void OSAR_scatter(
    const float* __restrict__ inputs, const float* __restrict__ memory,
    const float* __restrict__ bias, float* __restrict__ out)
{
    const int cid = blockIdx.x;
    const int sid = cid >> 2;
    const int y   = cid & 3;
    const int tid = threadIdx.x;
    float4* out4 = (float4*)out;

    if (sid < N_SRC_MEM1) {
        const int r = sid + 1;                        // memory row 1..511
        const int cnt = min(r, 128);
        const float4 v = ((const float4*)(memory + (size_t)r * F))[tid];
        for (int b = y; b < cnt; b += FAN)
            out4[(size_t)(b * 1024 + (r - b - 1)) * 256 + tid] = v;
    } else if (sid < N_SRC_MEM1 + N_SRC_MEM2) {
        const int d = sid - N_SRC_MEM1;               // 0..507
        const int cnt = min(d >> 2, 126) + 1;
        const float4 v = ((const float4*)(memory + (size_t)(516 + d) * F))[tid];
        for (int b = y; b < cnt; b += FAN)
            out4[(size_t)(b * 1024 + 512 + d - 4 * b) * 256 + tid] = v;
    } else if (sid < N_SRC_MEM1 + N_SRC_MEM2 + N_SRC_INP) {
        const int j = sid - (N_SRC_MEM1 + N_SRC_MEM2);   // 0..511
        const int b0 = j >> 2;
        const float4 v = ((const float4*)(inputs + (size_t)j * F))[tid];
        for (int b = b0 + y; b < 128; b += FAN)
            out4[(size_t)(b * 1024 + 1020 - 4 * b + j) * 256 + tid] = v;
    } else {
        const int c = sid - (N_SRC_MEM1 + N_SRC_MEM2 + N_SRC_INP);   // 0..127
        // combine split-K partials + bias inline
        float4 v = ((const float4*)bias)[tid];
#pragma unroll
        for (int z = 0; z < SPLITK; z++) {
            float4 p = ((const float4*)g_part[z][c])[tid];
            v.x += p.x; v.y += p.y; v.z += p.z; v.w += p.w;
        }
        for (int b = c + y; b < 128; b += FAN)
            out4[(size_t)(b * 1024 + 511 - b + c) * 256 + tid] = v;
    }
}

// ---------------------------------------------------------------------------
extern "C" void kernel_launch(void* const* d_in, const int* in_sizes, int n_in,
                              void* d_out, int out_size) {
    const float* inputs = (const float*)d_in[0];   // (128, 4, 1024)
    const float* memory = (const float*)d_in[1];   // (1024, 1024)
    const float* kern   = (const float*)d_in[2];   // (4, 1024, 1024)
    const float* bias   = (const float*)d_in[3];   // (1024,)
    float* out = (float*)d_out;                    // (128, 1024, 1024)

    dim3 ggemm(16, 2, SPLITK);
    OSAR_gemm<<<ggemm, 256>>>(memory + 512 * F, kern);
    OSAR_scatter<<<SCATTER_BLOCKS, 256>>>(inputs, memory, bias, out);
}

// round 12
// speedup vs baseline: 1.9864x; 1.1509x over previous
#include <cuda_runtime.h>

#define F 1024
#define KDIM 4096            // 4 * F
#define SPLITK 8
#define KCHUNK 512           // KDIM / SPLITK
#define NTILES 32            // KCHUNK / 16

#define GEMM_BLOCKS 256      // (N/64=16) x (M/64=2) x SPLITK=8
#define N_SRC_MEM1 511
#define N_SRC_MEM2 508
#define N_SRC_INP  512
#define FAN 4
#define SCATTER_BASE GEMM_BLOCKS                                        // 256
#define NONCOMP_BLOCKS ((N_SRC_MEM1 + N_SRC_MEM2 + N_SRC_INP) * FAN)    // 6124
#define COMP_BASE (SCATTER_BASE + NONCOMP_BLOCKS)                       // 6380
#define COMP_BLOCKS (128 * FAN)                                         // 512
#define TOTAL_BLOCKS (COMP_BASE + COMP_BLOCKS)                          // 6892

// Scratch (no cudaMalloc allowed)
__device__ float g_part[SPLITK][128][F];     // 4 MB split-K partials
__device__ unsigned g_flag;                  // GEMM done counter

// ---------------------------------------------------------------------------
// One fused kernel.
//   blocks [0,256)       : split-K fp32 GEMM part[kz] = X[128,4096]@W[4096,1024]
//                          64x64 tile, BK=16, double-buffered smem + register
//                          prefetch (latency-tolerant -> survives congestion).
//   blocks [256,6380)    : scatter-copy of rows NOT depending on comp.
//   blocks [6380,6892)   : comp rows (grid tail): wait on g_flag, combine
//                          split-K partials + bias inline, scatter.
// The wait cannot deadlock: GEMM blocks have the lowest block indices, so
// they are resident in wave 1 before any comp-tail block is scheduled.
// Scatter map (inversion of the gather; each source row read ONCE):
//   memory[r], r=1..511   -> (b, r-b-1)       for b = 0..min(r-1,127)
//   memory[516+d], d<508  -> (b, 512+d-4b)    for b = 0..(d>>2) [<=126]
//   inputs[j],  j=0..511  -> (b, 1020-4b+j)   for b = (j>>2)..127
//   comp[c],    c=0..127  -> (b, 511-b+c)     for b = c..127
// ---------------------------------------------------------------------------
__global__ __launch_bounds__(256) void OSAR_fused(
    const float* __restrict__ inputs, const float* __restrict__ memory,
    const float* __restrict__ W, const float* __restrict__ bias,
    float* __restrict__ out)
{
    const int bid = blockIdx.x;
    const int tid = threadIdx.x;

    __shared__ float As[2][16][64];   // As[buf][k][m]  (A transposed)
    __shared__ float Bs[2][16][64];   // Bs[buf][k][n]

    // ================= GEMM blocks =================
    if (bid < GEMM_BLOCKS) {
        const int kz = bid & 7;
        const int bn = (bid >> 3) & 15;
        const int bm = bid >> 7;

        const float* Xb = memory + 512 * F + bm * 64 * KDIM + kz * KCHUNK;
        const float* Wb = W + (size_t)kz * KCHUNK * F + bn * 64;

        const int ar  = tid >> 2, ak  = tid & 3;    // A load: m-row, k float4 slot
        const int brk = tid >> 4, bn4 = tid & 15;   // B load: k-row, n float4 slot
        const int ty  = tid >> 4, tx  = tid & 15;   // 16x16 microtile grid

        float acc[4][4] = {};

        float4 av = *(const float4*)(Xb + ar * KDIM + ak * 4);
        float4 bv = *(const float4*)(Wb + (size_t)brk * F + bn4 * 4);
        As[0][ak * 4 + 0][ar] = av.x;
        As[0][ak * 4 + 1][ar] = av.y;
        As[0][ak * 4 + 2][ar] = av.z;
        As[0][ak * 4 + 3][ar] = av.w;
        *(float4*)&Bs[0][brk][bn4 * 4] = bv;
        __syncthreads();

        int cur = 0;
        for (int t = 0; t < NTILES; t++) {
            if (t + 1 < NTILES) {   // prefetch next tile into registers
                av = *(const float4*)(Xb + ar * KDIM + (t + 1) * 16 + ak * 4);
                bv = *(const float4*)(Wb + (size_t)((t + 1) * 16 + brk) * F + bn4 * 4);
            }
#pragma unroll
            for (int k = 0; k < 16; k++) {
                float4 a = *(float4*)&As[cur][k][ty * 4];
                float4 b = *(float4*)&Bs[cur][k][tx * 4];
                acc[0][0] += a.x * b.x; acc[0][1] += a.x * b.y;
                acc[0][2] += a.x * b.z; acc[0][3] += a.x * b.w;
                acc[1][0] += a.y * b.x; acc[1][1] += a.y * b.y;
                acc[1][2] += a.y * b.z; acc[1][3] += a.y * b.w;
                acc[2][0] += a.z * b.x; acc[2][1] += a.z * b.y;
                acc[2][2] += a.z * b.z; acc[2][3] += a.z * b.w;
                acc[3][0] += a.w * b.x; acc[3][1] += a.w * b.y;
                acc[3][2] += a.w * b.z; acc[3][3] += a.w * b.w;
            }
            if (t + 1 < NTILES) {
                int nxt = cur ^ 1;
                As[nxt][ak * 4 + 0][ar] = av.x;
                As[nxt][ak * 4 + 1][ar] = av.y;
                As[nxt][ak * 4 + 2][ar] = av.z;
                As[nxt][ak * 4 + 3][ar] = av.w;
                *(float4*)&Bs[nxt][brk][bn4 * 4] = bv;
            }
            __syncthreads();
            cur ^= 1;
        }

        float* dst = &g_part[kz][bm * 64 + ty * 4][bn * 64 + tx * 4];
#pragma unroll
        for (int i = 0; i < 4; i++)
            *(float4*)(dst + (size_t)i * F) =
                make_float4(acc[i][0], acc[i][1], acc[i][2], acc[i][3]);

        __syncthreads();
        if (tid == 0) { __threadfence(); atomicAdd(&g_flag, 1u); }
        return;
    }

    float4* out4 = (float4*)out;

    // ================= non-comp scatter blocks =================
    if (bid < COMP_BASE) {
        const int cid = bid - SCATTER_BASE;
        const int sid = cid >> 2;
        const int y   = cid & 3;

        if (sid < N_SRC_MEM1) {
            const int r = sid + 1;                        // memory row 1..511
            const int cnt = min(r, 128);
            const float4 v = ((const float4*)(memory + (size_t)r * F))[tid];
            for (int b = y; b < cnt; b += FAN)
                out4[(size_t)(b * 1024 + (r - b - 1)) * 256 + tid] = v;
        } else if (sid < N_SRC_MEM1 + N_SRC_MEM2) {
            const int d = sid - N_SRC_MEM1;               // 0..507
            const int cnt = min(d >> 2, 126) + 1;
            const float4 v = ((const float4*)(memory + (size_t)(516 + d) * F))[tid];
            for (int b = y; b < cnt; b += FAN)
                out4[(size_t)(b * 1024 + 512 + d - 4 * b) * 256 + tid] = v;
        } else {
            const int j = sid - (N_SRC_MEM1 + N_SRC_MEM2);   // 0..511
            const int b0 = j >> 2;
            const float4 v = ((const float4*)(inputs + (size_t)j * F))[tid];
            for (int b = b0 + y; b < 128; b += FAN)
                out4[(size_t)(b * 1024 + 1020 - 4 * b + j) * 256 + tid] = v;
        }
        return;
    }

    // ================= comp scatter blocks (grid tail) =================
    {
        const int cid = bid - COMP_BASE;
        const int c = cid >> 2;       // comp row 0..127
        const int y = cid & 3;

        if (tid == 0) {
            volatile unsigned* f = &g_flag;
            while (*f < GEMM_BLOCKS) __nanosleep(128);
            __threadfence();
        }
        __syncthreads();

        float4 v = ((const float4*)bias)[tid];
#pragma unroll
        for (int z = 0; z < SPLITK; z++) {
            float4 p = ((const float4*)g_part[z][c])[tid];
            v.x += p.x; v.y += p.y; v.z += p.z; v.w += p.w;
        }
        for (int b = c + y; b < 128; b += FAN)
            out4[(size_t)(b * 1024 + 511 - b + c) * 256 + tid] = v;
    }
}

// ---------------------------------------------------------------------------
extern "C" void kernel_launch(void* const* d_in, const int* in_sizes, int n_in,
                              void* d_out, int out_size) {
    const float* inputs = (const float*)d_in[0];   // (128, 4, 1024)
    const float* memory = (const float*)d_in[1];   // (1024, 1024)
    const float* kern   = (const float*)d_in[2];   // (4, 1024, 1024)
    const float* bias   = (const float*)d_in[3];   // (1024,)
    float* out = (float*)d_out;                    // (128, 1024, 1024)

    void* flagAddr = nullptr;
    cudaGetSymbolAddress(&flagAddr, g_flag);
    cudaMemsetAsync(flagAddr, 0, sizeof(unsigned));

    OSAR_fused<<<TOTAL_BLOCKS, 256>>>(inputs, memory, kern, bias, out);
}